// round 2
// baseline (speedup 1.0000x reference)
#include <cuda_runtime.h>
#include <cstdint>

// Problem constants
#define B_       128
#define T_IN     240
#define T_OUT    30
#define D_       128
#define H_       256
#define G3       768              // 3*H
#define STRIDE_  8
#define ENC_STEPS (T_IN * B_)     // 30720
#define DEC_STEPS (T_OUT * B_)    // 3840

// Scratch: precomputed input projections gi = x @ Wih^T + b_ih
__device__ float GI_enc[ENC_STEPS * G3];   // ~94.4 MB
__device__ float GI_dec[DEC_STEPS * G3];   // ~11.8 MB

// ---------------------------------------------------------------------------
// Kernel 1: GI GEMM.  GI[s][row] = b_ih[row] + sum_d X[s,d] * Wih[row][d]
// ---------------------------------------------------------------------------
#define S_TILE     32
#define ENC_BLOCKS (ENC_STEPS / S_TILE)   // 960
#define DEC_BLOCKS (DEC_STEPS / S_TILE)   // 120

__global__ void __launch_bounds__(768, 1) gi_kernel(
    const float* __restrict__ x,
    const float* __restrict__ Wih_e, const float* __restrict__ bih_e,
    const float* __restrict__ Wih_d, const float* __restrict__ bih_d)
{
    __shared__ __align__(16) float Xs[S_TILE][D_];   // 16 KB

    bool enc = blockIdx.x < ENC_BLOCKS;
    int  sblk = enc ? blockIdx.x : blockIdx.x - ENC_BLOCKS;
    int  s0   = sblk * S_TILE;
    const float* W   = enc ? Wih_e : Wih_d;
    const float* bih = enc ? bih_e : bih_d;
    float*       GI  = enc ? GI_enc : GI_dec;
    int tstride = enc ? 1 : STRIDE_;

    int tid = threadIdx.x;

    for (int idx = tid; idx < S_TILE * D_; idx += 768) {
        int i = idx >> 7;
        int k = idx & 127;
        int s = s0 + i;
        int b = s & 127;
        int t = (s >> 7) * tstride;
        Xs[i][k] = x[(size_t)b * (T_IN * D_) + (size_t)t * D_ + k];
    }
    __syncthreads();

    int row = tid;
    const float4* W4 = (const float4*)(W + (size_t)row * D_);

    float acc[S_TILE];
#pragma unroll
    for (int i = 0; i < S_TILE; i++) acc[i] = 0.f;

#pragma unroll 4
    for (int kk = 0; kk < D_ / 4; kk++) {
        float4 w = W4[kk];
#pragma unroll
        for (int i = 0; i < S_TILE; i++) {
            float4 xv = ((const float4*)Xs[i])[kk];
            acc[i] += w.x * xv.x + w.y * xv.y + w.z * xv.z + w.w * xv.w;
        }
    }

    float bv = bih[row];
#pragma unroll
    for (int i = 0; i < S_TILE; i++)
        GI[(size_t)(s0 + i) * G3 + row] = acc[i] + bv;
}

// ---------------------------------------------------------------------------
// Kernel 2: serial GRU scans.  8-CTA cluster, register-resident W_hh,
// fma.rn.f32x2 matvec, mbarrier-based cross-CTA sync (no cluster.sync in
// the step loop).
// ---------------------------------------------------------------------------
#define CLUSTER  8
#define NTHREADS 384

__device__ __forceinline__ uint32_t smem_u32(const void* p) {
    return (uint32_t)__cvta_generic_to_shared(p);
}
__device__ __forceinline__ uint32_t mapa_shared(uint32_t addr, uint32_t rank) {
    uint32_t r;
    asm volatile("mapa.shared::cluster.u32 %0, %1, %2;" : "=r"(r) : "r"(addr), "r"(rank));
    return r;
}
__device__ __forceinline__ void st_cluster_f32(uint32_t addr, float v) {
    asm volatile("st.shared::cluster.f32 [%0], %1;" :: "r"(addr), "f"(v) : "memory");
}
__device__ __forceinline__ void cluster_sync_() {
    asm volatile("barrier.cluster.arrive.aligned;" ::: "memory");
    asm volatile("barrier.cluster.wait.aligned;"   ::: "memory");
}
__device__ __forceinline__ void mbar_init_(uint32_t addr, uint32_t count) {
    asm volatile("mbarrier.init.shared.b64 [%0], %1;" :: "r"(addr), "r"(count) : "memory");
}
__device__ __forceinline__ void mbar_arrive_remote_(uint32_t addr) {
    asm volatile("mbarrier.arrive.release.cluster.shared::cluster.b64 _, [%0];"
                 :: "r"(addr) : "memory");
}
__device__ __forceinline__ void mbar_wait_(uint32_t addr, uint32_t parity) {
    asm volatile(
        "{\n\t"
        ".reg .pred P;\n\t"
        "W_%=:\n\t"
        "mbarrier.try_wait.parity.acquire.cluster.shared::cta.b64 P, [%0], %1, 0x989680;\n\t"
        "@!P bra W_%=;\n\t"
        "}"
        :: "r"(addr), "r"(parity) : "memory");
}
__device__ __forceinline__ void fma2_(unsigned long long& acc,
                                      unsigned long long a, unsigned long long b) {
    asm("fma.rn.f32x2 %0, %1, %2, %0;" : "+l"(acc) : "l"(a), "l"(b));
}
__device__ __forceinline__ float2 unpack2_(unsigned long long v) {
    float2 f;
    asm("mov.b64 {%0, %1}, %2;" : "=f"(f.x), "=f"(f.y) : "l"(v));
    return f;
}
__device__ __forceinline__ float sigmoid_(float xv) {
    return __fdividef(1.0f, 1.0f + __expf(-xv));
}
__device__ __forceinline__ float tanh_(float xv) {
    return 1.0f - __fdividef(2.0f, __expf(2.0f * xv) + 1.0f);
}

__global__ void __launch_bounds__(NTHREADS, 1) scan_kernel(
    const float* __restrict__ Whh_e, const float* __restrict__ bhh_e,
    const float* __restrict__ Whh_d, const float* __restrict__ bhh_d,
    float* __restrict__ out)
{
    __shared__ __align__(16) float hbuf[2][H_];
    __shared__ float partial[NTHREADS];
    __shared__ __align__(8) unsigned long long mbar[2];

    bool enc = (blockIdx.x >> 3) == 0;
    uint32_t crank;
    asm("mov.u32 %0, %%cluster_ctarank;" : "=r"(crank));

    const float* Whh = enc ? Whh_e : Whh_d;
    const float* bhh = enc ? bhh_e : bhh_d;
    const float* GI  = enc ? GI_enc : GI_dec;
    int    nsteps = enc ? ENC_STEPS : DEC_STEPS;
    float* outp   = enc ? out : (out + 240 * H_);

    int tid  = threadIdx.x;
    int l    = tid % 96;        // local weight row
    int q    = tid / 96;        // input quarter (0..3), warp-uniform
    int part = l >> 5;          // 0=r,1=z,2=n
    int i0l  = l & 31;
    int Grow = part * 256 + (int)crank * 32 + i0l;   // global W_hh row

    // ---- load this thread's 64 weights as 32 packed f32x2 ----
    unsigned long long w2[32];
    {
        const ulonglong2* Wr = (const ulonglong2*)(Whh + (size_t)Grow * H_ + q * 64);
#pragma unroll
        for (int kk = 0; kk < 16; kk++) {
            ulonglong2 v = Wr[kk];
            w2[2 * kk]     = v.x;
            w2[2 * kk + 1] = v.y;
        }
    }

    // ---- gate-lane (warp 0) setup ----
    bool gatelane = (tid < 32);
    int  j = (int)crank * 32 + tid;   // global h index (gate lanes)
    float bh_r = 0.f, bh_z = 0.f, bh_n = 0.f;
    uint32_t remH0[CLUSTER], remH1[CLUSTER];
    uint32_t remB0 = 0, remB1 = 0;
    if (gatelane) {
        bh_r = bhh[j];
        bh_z = bhh[256 + j];
        bh_n = bhh[512 + j];
        uint32_t a0 = smem_u32(&hbuf[0][j]);
        uint32_t a1 = smem_u32(&hbuf[1][j]);
#pragma unroll
        for (int rk = 0; rk < CLUSTER; rk++) {
            remH0[rk] = mapa_shared(a0, rk);
            remH1[rk] = mapa_shared(a1, rk);
        }
        if (tid < CLUSTER) {
            remB0 = mapa_shared(smem_u32(&mbar[0]), (uint32_t)tid);
            remB1 = mapa_shared(smem_u32(&mbar[1]), (uint32_t)tid);
        }
    }
    uint32_t mbar_local[2] = { smem_u32(&mbar[0]), smem_u32(&mbar[1]) };

    // init: h0 = 0, mbarriers expect 8 arrivals (one per producer CTA)
    if (tid < H_) hbuf[0][tid] = 0.f;
    if (tid == 0) {
        mbar_init_(mbar_local[0], CLUSTER);
        mbar_init_(mbar_local[1], CLUSTER);
    }
    __syncthreads();
    cluster_sync_();   // all inits visible before any remote store/arrive

    // gi prefetch, distance 2
    float g0r = 0.f, g0z = 0.f, g0n = 0.f;
    float g1r = 0.f, g1z = 0.f, g1n = 0.f;
    if (gatelane) {
        g0r = __ldg(&GI[j]);
        g0z = __ldg(&GI[256 + j]);
        g0n = __ldg(&GI[512 + j]);
        if (nsteps > 1) {
            const float* g = GI + (size_t)G3;
            g1r = __ldg(&g[j]);
            g1z = __ldg(&g[256 + j]);
            g1n = __ldg(&g[512 + j]);
        }
    }

    for (int s = 0; s < nsteps; s++) {
        int rd = s & 1;           // h(s-1) lives in hbuf[rd]
        int wr = rd ^ 1;          // h(s) goes to hbuf[wr]

        if (s > 0) {
            // wait for h(s-1): barrier (s-1)&1, parity ((s-1)>>1)&1
            mbar_wait_(mbar_local[(s - 1) & 1], (uint32_t)(((s - 1) >> 1) & 1));
        }

        // ---- matvec: packed f32x2 dot over this thread's 64-wide h segment
        const ulonglong2* hp = (const ulonglong2*)(&hbuf[rd][q * 64]);
        unsigned long long a0 = 0ull, a1 = 0ull, a2 = 0ull, a3 = 0ull;
#pragma unroll
        for (int kk = 0; kk < 16; kk++) {
            ulonglong2 hv = hp[kk];
            if (kk & 1) { fma2_(a2, w2[2 * kk], hv.x); fma2_(a3, w2[2 * kk + 1], hv.y); }
            else        { fma2_(a0, w2[2 * kk], hv.x); fma2_(a1, w2[2 * kk + 1], hv.y); }
        }
        {
            float2 f0 = unpack2_(a0), f1 = unpack2_(a1);
            float2 f2 = unpack2_(a2), f3 = unpack2_(a3);
            partial[tid] = ((f0.x + f0.y) + (f1.x + f1.y))
                         + ((f2.x + f2.y) + (f3.x + f3.y));
        }

        // prefetch gi for step s+2
        float nr = 0.f, nz = 0.f, nn = 0.f;
        if (gatelane && (s + 2) < nsteps) {
            const float* g = GI + (size_t)(s + 2) * G3;
            nr = __ldg(&g[j]);
            nz = __ldg(&g[256 + j]);
            nn = __ldg(&g[512 + j]);
        }

        // partial[] handoff: producers arrive (non-blocking), gate warp syncs
        if (tid < 32) {
            asm volatile("bar.sync 1, %0;" :: "n"(NTHREADS) : "memory");
        } else {
            asm volatile("bar.arrive 1, %0;" :: "n"(NTHREADS) : "memory");
        }

        if (gatelane) {
            int i0 = tid;
            float pr = 0.f, pz = 0.f, pn = 0.f;
#pragma unroll
            for (int qq = 0; qq < 4; qq++) {
                pr += partial[qq * 96 + i0];
                pz += partial[qq * 96 + 32 + i0];
                pn += partial[qq * 96 + 64 + i0];
            }
            float r    = sigmoid_(g0r + pr + bh_r);
            float z    = sigmoid_(g0z + pz + bh_z);
            float hold = hbuf[rd][j];
            float n    = tanh_(g0n + r * (pn + bh_n));
            float hnew = n + z * (hold - n);   // (1-z)*n + z*h

            if ((s + 1) < nsteps) {
                // broadcast h_new[j] into every CTA's write buffer
                if (wr == 0) {
#pragma unroll
                    for (int rk = 0; rk < CLUSTER; rk++) st_cluster_f32(remH0[rk], hnew);
                } else {
#pragma unroll
                    for (int rk = 0; rk < CLUSTER; rk++) st_cluster_f32(remH1[rk], hnew);
                }
                __syncwarp();
                // lanes 0..7: one release-arrive each, at CTA(lane)'s barrier s&1
                if (tid < CLUSTER) {
                    mbar_arrive_remote_((s & 1) ? remB1 : remB0);
                }
            }

            // outputs
            if (enc) {
                if ((s & 127) == 127)
                    outp[(size_t)(s >> 7) * H_ + j] = hnew;
            } else {
                outp[(size_t)(s & 127) * (T_OUT * H_) + (size_t)(s >> 7) * H_ + j] = hnew;
            }

            // rotate gi prefetch ring
            g0r = g1r; g0z = g1z; g0n = g1n;
            g1r = nr;  g1z = nz;  g1n = nn;
        }
    }

    cluster_sync_();   // no CTA exits while peer DSMEM stores may be in flight
}

// ---------------------------------------------------------------------------
// Launch
// ---------------------------------------------------------------------------
extern "C" void kernel_launch(void* const* d_in, const int* in_sizes, int n_in,
                              void* d_out, int out_size)
{
    const float* x     = (const float*)d_in[0];
    const float* Wih_e = (const float*)d_in[1];
    const float* Whh_e = (const float*)d_in[2];
    const float* bih_e = (const float*)d_in[3];
    const float* bhh_e = (const float*)d_in[4];
    const float* Wih_d = (const float*)d_in[5];
    const float* Whh_d = (const float*)d_in[6];
    const float* bih_d = (const float*)d_in[7];
    const float* bhh_d = (const float*)d_in[8];
    float* out = (float*)d_out;

    gi_kernel<<<ENC_BLOCKS + DEC_BLOCKS, 768>>>(x, Wih_e, bih_e, Wih_d, bih_d);

    cudaLaunchConfig_t cfg = {};
    cfg.gridDim  = dim3(2 * CLUSTER, 1, 1);
    cfg.blockDim = dim3(NTHREADS, 1, 1);
    cfg.dynamicSmemBytes = 0;
    cfg.stream = 0;
    cudaLaunchAttribute attrs[1];
    attrs[0].id = cudaLaunchAttributeClusterDimension;
    attrs[0].val.clusterDim.x = CLUSTER;
    attrs[0].val.clusterDim.y = 1;
    attrs[0].val.clusterDim.z = 1;
    cfg.attrs = attrs;
    cfg.numAttrs = 1;
    cudaLaunchKernelEx(&cfg, scan_kernel, Whh_e, bhh_e, Whh_d, bhh_d, out);
}

// round 3
// speedup vs baseline: 1.0272x; 1.0272x over previous
#include <cuda_runtime.h>
#include <cstdint>

// Problem constants
#define B_       128
#define T_IN     240
#define T_OUT    30
#define D_       128
#define H_       256
#define G3       768              // 3*H
#define STRIDE_  8
#define ENC_STEPS (T_IN * B_)     // 30720
#define DEC_STEPS (T_OUT * B_)    // 3840

// Scratch: precomputed input projections gi = x @ Wih^T + b_ih
__device__ float GI_enc[ENC_STEPS * G3];   // ~94.4 MB
__device__ float GI_dec[DEC_STEPS * G3];   // ~11.8 MB

// ---------------------------------------------------------------------------
// Kernel 1: GI GEMM.  GI[s][row] = b_ih[row] + sum_d X[s,d] * Wih[row][d]
// ---------------------------------------------------------------------------
#define S_TILE     32
#define ENC_BLOCKS (ENC_STEPS / S_TILE)   // 960
#define DEC_BLOCKS (DEC_STEPS / S_TILE)   // 120

__global__ void __launch_bounds__(768, 1) gi_kernel(
    const float* __restrict__ x,
    const float* __restrict__ Wih_e, const float* __restrict__ bih_e,
    const float* __restrict__ Wih_d, const float* __restrict__ bih_d)
{
    __shared__ __align__(16) float Xs[S_TILE][D_];   // 16 KB

    bool enc = blockIdx.x < ENC_BLOCKS;
    int  sblk = enc ? blockIdx.x : blockIdx.x - ENC_BLOCKS;
    int  s0   = sblk * S_TILE;
    const float* W   = enc ? Wih_e : Wih_d;
    const float* bih = enc ? bih_e : bih_d;
    float*       GI  = enc ? GI_enc : GI_dec;
    int tstride = enc ? 1 : STRIDE_;

    int tid = threadIdx.x;

    for (int idx = tid; idx < S_TILE * D_; idx += 768) {
        int i = idx >> 7;
        int k = idx & 127;
        int s = s0 + i;
        int b = s & 127;
        int t = (s >> 7) * tstride;
        Xs[i][k] = x[(size_t)b * (T_IN * D_) + (size_t)t * D_ + k];
    }
    __syncthreads();

    int row = tid;
    const float4* W4 = (const float4*)(W + (size_t)row * D_);

    float acc[S_TILE];
#pragma unroll
    for (int i = 0; i < S_TILE; i++) acc[i] = 0.f;

#pragma unroll 4
    for (int kk = 0; kk < D_ / 4; kk++) {
        float4 w = W4[kk];
#pragma unroll
        for (int i = 0; i < S_TILE; i++) {
            float4 xv = ((const float4*)Xs[i])[kk];
            acc[i] += w.x * xv.x + w.y * xv.y + w.z * xv.z + w.w * xv.w;
        }
    }

    float bv = bih[row];
#pragma unroll
    for (int i = 0; i < S_TILE; i++)
        GI[(size_t)(s0 + i) * G3 + row] = acc[i] + bv;
}

// ---------------------------------------------------------------------------
// Kernel 2: serial GRU scans.  8-CTA cluster, register-resident W_hh.
// Thread layout (256 threads/CTA):
//   warp w (0..7), lane: o = lane>>2 (column slice, 0..7), jq = lane&3
//   j = crank*32 + w*4 + jq  (output index), cols [o*32, o*32+32)
// Each thread holds rows {j, 256+j, 512+j} x 32 cols = 96 weights (48 f32x2).
// Cross-slice reduce: 3x shfl.bfly (xor 4,8,16).  Every lane then has the
// full gh(r,z,n) for its j -> gates computed redundantly, and each lane
// issues exactly ONE st.shared::cluster (to CTA o).  One cluster barrier
// per step, no intra-CTA barrier.
// ---------------------------------------------------------------------------
#define CLUSTER  8
#define NTHREADS 256

__device__ __forceinline__ uint32_t smem_u32(const void* p) {
    return (uint32_t)__cvta_generic_to_shared(p);
}
__device__ __forceinline__ uint32_t mapa_shared(uint32_t addr, uint32_t rank) {
    uint32_t r;
    asm volatile("mapa.shared::cluster.u32 %0, %1, %2;" : "=r"(r) : "r"(addr), "r"(rank));
    return r;
}
__device__ __forceinline__ void st_cluster_f32(uint32_t addr, float v) {
    asm volatile("st.shared::cluster.f32 [%0], %1;" :: "r"(addr), "f"(v) : "memory");
}
__device__ __forceinline__ void cluster_arrive_() {
    asm volatile("barrier.cluster.arrive.aligned;" ::: "memory");
}
__device__ __forceinline__ void cluster_wait_() {
    asm volatile("barrier.cluster.wait.aligned;" ::: "memory");
}
__device__ __forceinline__ void fma2_(unsigned long long& acc,
                                      unsigned long long a, unsigned long long b) {
    asm("fma.rn.f32x2 %0, %1, %2, %0;" : "+l"(acc) : "l"(a), "l"(b));
}
__device__ __forceinline__ float hsum2_(unsigned long long v) {
    float lo, hi;
    asm("mov.b64 {%0, %1}, %2;" : "=f"(lo), "=f"(hi) : "l"(v));
    return lo + hi;
}
__device__ __forceinline__ float sigmoid_(float xv) {
    return __fdividef(1.0f, 1.0f + __expf(-xv));
}
__device__ __forceinline__ float tanh_(float xv) {
    return 1.0f - __fdividef(2.0f, __expf(2.0f * xv) + 1.0f);
}

__global__ void __launch_bounds__(NTHREADS, 1) scan_kernel(
    const float* __restrict__ Whh_e, const float* __restrict__ bhh_e,
    const float* __restrict__ Whh_d, const float* __restrict__ bhh_d,
    float* __restrict__ out)
{
    __shared__ __align__(16) float hbuf[2][H_];

    bool enc = (blockIdx.x >> 3) == 0;
    uint32_t crank;
    asm("mov.u32 %0, %%cluster_ctarank;" : "=r"(crank));

    const float* Whh = enc ? Whh_e : Whh_d;
    const float* bhh = enc ? bhh_e : bhh_d;
    const float* GI  = enc ? GI_enc : GI_dec;
    int    nsteps = enc ? ENC_STEPS : DEC_STEPS;
    float* outp   = enc ? out : (out + 240 * H_);

    int tid  = threadIdx.x;
    int w    = tid >> 5;
    int lane = tid & 31;
    int o    = lane >> 2;             // column slice / target CTA rank
    int jloc = w * 4 + (lane & 3);    // local output index 0..31
    int j    = (int)crank * 32 + jloc;

    // ---- load this thread's 96 weights as 48 packed f32x2 ----
    unsigned long long wr_[16], wz_[16], wn_[16];
    {
        const ulonglong2* Pr = (const ulonglong2*)(Whh + (size_t)j * H_ + o * 32);
        const ulonglong2* Pz = (const ulonglong2*)(Whh + (size_t)(256 + j) * H_ + o * 32);
        const ulonglong2* Pn = (const ulonglong2*)(Whh + (size_t)(512 + j) * H_ + o * 32);
#pragma unroll
        for (int k = 0; k < 8; k++) {
            ulonglong2 vr = Pr[k]; wr_[2*k] = vr.x; wr_[2*k+1] = vr.y;
            ulonglong2 vz = Pz[k]; wz_[2*k] = vz.x; wz_[2*k+1] = vz.y;
            ulonglong2 vn = Pn[k]; wn_[2*k] = vn.x; wn_[2*k+1] = vn.y;
        }
    }

    float bh_r = bhh[j];
    float bh_z = bhh[256 + j];
    float bh_n = bhh[512 + j];

    // remote store addresses: hbuf[buf][j] in CTA rank o
    uint32_t remA0 = mapa_shared(smem_u32(&hbuf[0][j]), (uint32_t)o);
    uint32_t remA1 = mapa_shared(smem_u32(&hbuf[1][j]), (uint32_t)o);

    // init h0 = 0
    hbuf[0][tid] = 0.f;
    __syncthreads();
    cluster_arrive_();
    cluster_wait_();

    // gi prefetch ring, distance 2
    float g0r = __ldg(&GI[j]);
    float g0z = __ldg(&GI[256 + j]);
    float g0n = __ldg(&GI[512 + j]);
    float g1r = 0.f, g1z = 0.f, g1n = 0.f;
    if (nsteps > 1) {
        const float* g = GI + (size_t)G3;
        g1r = __ldg(&g[j]);
        g1z = __ldg(&g[256 + j]);
        g1n = __ldg(&g[512 + j]);
    }

    for (int s = 0; s < nsteps; s++) {
        int rd = s & 1;           // h(s-1) lives in hbuf[rd]
        int wrb = rd ^ 1;         // h(s) goes to hbuf[wrb]

        // issue gi prefetch for s+2 BEFORE the barrier wait (hides DRAM)
        float nr = 0.f, nz = 0.f, nn = 0.f;
        if ((s + 2) < nsteps) {
            const float* g = GI + (size_t)(s + 2) * G3;
            nr = __ldg(&g[j]);
            nz = __ldg(&g[256 + j]);
            nn = __ldg(&g[512 + j]);
        }

        if (s > 0) cluster_wait_();   // h(s-1) now visible in local hbuf[rd]

        // ---- matvec over this thread's 32-col slice (3 rows) ----
        const ulonglong2* hp = (const ulonglong2*)(&hbuf[rd][o * 32]);
        float hold = hbuf[rd][j];
        unsigned long long ar0 = 0ull, ar1 = 0ull;
        unsigned long long az0 = 0ull, az1 = 0ull;
        unsigned long long an0 = 0ull, an1 = 0ull;
#pragma unroll
        for (int k = 0; k < 8; k++) {
            ulonglong2 hv = hp[k];
            fma2_(ar0, wr_[2*k], hv.x); fma2_(ar1, wr_[2*k+1], hv.y);
            fma2_(az0, wz_[2*k], hv.x); fma2_(az1, wz_[2*k+1], hv.y);
            fma2_(an0, wn_[2*k], hv.x); fma2_(an1, wn_[2*k+1], hv.y);
        }
        float pr = hsum2_(ar0) + hsum2_(ar1);
        float pz = hsum2_(az0) + hsum2_(az1);
        float pn = hsum2_(an0) + hsum2_(an1);

        // ---- butterfly reduce over the 8 column slices (lanes xor 4,8,16)
#pragma unroll
        for (int d = 4; d < 32; d <<= 1) {
            pr += __shfl_xor_sync(0xffffffffu, pr, d);
            pz += __shfl_xor_sync(0xffffffffu, pz, d);
            pn += __shfl_xor_sync(0xffffffffu, pn, d);
        }

        // ---- gates (every lane redundantly for its j) ----
        float r    = sigmoid_(g0r + pr + bh_r);
        float z    = sigmoid_(g0z + pz + bh_z);
        float n    = tanh_(g0n + r * (pn + bh_n));
        float hnew = n + z * (hold - n);   // (1-z)*n + z*h

        // ---- one remote store per lane: hnew(j) -> CTA o ----
        st_cluster_f32(wrb ? remA1 : remA0, hnew);

        // ---- outputs (lane group o==0 only: unique j per store) ----
        if (o == 0) {
            if (enc) {
                if ((s & 127) == 127)
                    outp[(size_t)(s >> 7) * H_ + j] = hnew;
            } else {
                outp[(size_t)(s & 127) * (T_OUT * H_) + (size_t)(s >> 7) * H_ + j] = hnew;
            }
        }

        // rotate gi ring
        g0r = g1r; g0z = g1z; g0n = g1n;
        g1r = nr;  g1z = nz;  g1n = nn;

        cluster_arrive_();   // release: h stores visible at wait of step s+1
    }

    cluster_wait_();   // match final arrive; no CTA exits with stores in flight
}

// ---------------------------------------------------------------------------
// Launch
// ---------------------------------------------------------------------------
extern "C" void kernel_launch(void* const* d_in, const int* in_sizes, int n_in,
                              void* d_out, int out_size)
{
    const float* x     = (const float*)d_in[0];
    const float* Wih_e = (const float*)d_in[1];
    const float* Whh_e = (const float*)d_in[2];
    const float* bih_e = (const float*)d_in[3];
    const float* bhh_e = (const float*)d_in[4];
    const float* Wih_d = (const float*)d_in[5];
    const float* Whh_d = (const float*)d_in[6];
    const float* bih_d = (const float*)d_in[7];
    const float* bhh_d = (const float*)d_in[8];
    float* out = (float*)d_out;

    gi_kernel<<<ENC_BLOCKS + DEC_BLOCKS, 768>>>(x, Wih_e, bih_e, Wih_d, bih_d);

    cudaLaunchConfig_t cfg = {};
    cfg.gridDim  = dim3(2 * CLUSTER, 1, 1);
    cfg.blockDim = dim3(NTHREADS, 1, 1);
    cfg.dynamicSmemBytes = 0;
    cfg.stream = 0;
    cudaLaunchAttribute attrs[1];
    attrs[0].id = cudaLaunchAttributeClusterDimension;
    attrs[0].val.clusterDim.x = CLUSTER;
    attrs[0].val.clusterDim.y = 1;
    attrs[0].val.clusterDim.z = 1;
    cfg.attrs = attrs;
    cfg.numAttrs = 1;
    cudaLaunchKernelEx(&cfg, scan_kernel, Whh_e, bhh_e, Whh_d, bhh_d, out);
}

// round 5
// speedup vs baseline: 1.4734x; 1.4344x over previous
#include <cuda_runtime.h>
#include <cstdint>

// Problem constants
#define B_       128
#define T_IN     240
#define T_OUT    30
#define D_       128
#define H_       256
#define G3       768              // 3*H
#define STRIDE_  8
#define ENC_STEPS (T_IN * B_)     // 30720
#define DEC_STEPS (T_OUT * B_)    // 3840

// Scratch: precomputed input projections gi = x @ Wih^T + b_ih
__device__ float GI_enc[ENC_STEPS * G3];   // ~94.4 MB
__device__ float GI_dec[DEC_STEPS * G3];   // ~11.8 MB

// ---------------------------------------------------------------------------
// Kernel 1: GI GEMM.  GI[s][row] = b_ih[row] + sum_d X[s,d] * Wih[row][d]
// ---------------------------------------------------------------------------
#define S_TILE     32
#define ENC_BLOCKS (ENC_STEPS / S_TILE)   // 960
#define DEC_BLOCKS (DEC_STEPS / S_TILE)   // 120

__global__ void __launch_bounds__(768, 1) gi_kernel(
    const float* __restrict__ x,
    const float* __restrict__ Wih_e, const float* __restrict__ bih_e,
    const float* __restrict__ Wih_d, const float* __restrict__ bih_d)
{
    __shared__ __align__(16) float Xs[S_TILE][D_];   // 16 KB

    bool enc = blockIdx.x < ENC_BLOCKS;
    int  sblk = enc ? blockIdx.x : blockIdx.x - ENC_BLOCKS;
    int  s0   = sblk * S_TILE;
    const float* W   = enc ? Wih_e : Wih_d;
    const float* bih = enc ? bih_e : bih_d;
    float*       GI  = enc ? GI_enc : GI_dec;
    int tstride = enc ? 1 : STRIDE_;

    int tid = threadIdx.x;

    for (int idx = tid; idx < S_TILE * D_; idx += 768) {
        int i = idx >> 7;
        int k = idx & 127;
        int s = s0 + i;
        int b = s & 127;
        int t = (s >> 7) * tstride;
        Xs[i][k] = x[(size_t)b * (T_IN * D_) + (size_t)t * D_ + k];
    }
    __syncthreads();

    int row = tid;
    const float4* W4 = (const float4*)(W + (size_t)row * D_);

    float acc[S_TILE];
#pragma unroll
    for (int i = 0; i < S_TILE; i++) acc[i] = 0.f;

#pragma unroll 4
    for (int kk = 0; kk < D_ / 4; kk++) {
        float4 w = W4[kk];
#pragma unroll
        for (int i = 0; i < S_TILE; i++) {
            float4 xv = ((const float4*)Xs[i])[kk];
            acc[i] += w.x * xv.x + w.y * xv.y + w.z * xv.z + w.w * xv.w;
        }
    }

    float bv = bih[row];
#pragma unroll
    for (int i = 0; i < S_TILE; i++)
        GI[(size_t)(s0 + i) * G3 + row] = acc[i] + bv;
}

// ---------------------------------------------------------------------------
// Kernel 2: serial GRU scans.  8-CTA cluster, register-resident W_hh.
// Cross-CTA h exchange via st.async.shared::cluster (data + mbarrier tx
// signal in ONE hardware op).  Two mbarriers ping-pong (barrier index ==
// h-buffer index).  No cluster barrier, no fence, no intra-CTA sync in loop.
//
// Thread layout (256 threads/CTA):
//   warp w (0..7), lane: o = lane>>2 (column slice & target CTA), jq = lane&3
//   j = crank*32 + w*4 + jq (output index), columns [o*32, o*32+32)
// Per step each consumer CTA receives exactly 256 floats = 1024 tx bytes
// (one st.async per thread cluster-wide with o == consumer rank).
// ---------------------------------------------------------------------------
#define CLUSTER  8
#define NTHREADS 256
#define TX_BYTES (H_ * 4)   // 1024

__device__ __forceinline__ uint32_t smem_u32(const void* p) {
    return (uint32_t)__cvta_generic_to_shared(p);
}
__device__ __forceinline__ uint32_t mapa_shared(uint32_t addr, uint32_t rank) {
    uint32_t r;
    asm volatile("mapa.shared::cluster.u32 %0, %1, %2;" : "=r"(r) : "r"(addr), "r"(rank));
    return r;
}
__device__ __forceinline__ void mbar_init_(uint32_t addr, uint32_t count) {
    asm volatile("mbarrier.init.shared.b64 [%0], %1;" :: "r"(addr), "r"(count) : "memory");
}
__device__ __forceinline__ void mbar_arm_(uint32_t addr, uint32_t tx) {
    asm volatile("mbarrier.arrive.expect_tx.shared.b64 _, [%0], %1;"
                 :: "r"(addr), "r"(tx) : "memory");
}
__device__ __forceinline__ void mbar_wait_(uint32_t addr, uint32_t parity) {
    asm volatile(
        "{\n\t"
        ".reg .pred P;\n\t"
        "W_%=:\n\t"
        "mbarrier.try_wait.parity.shared.b64 P, [%0], %1, 0x989680;\n\t"
        "@!P bra W_%=;\n\t"
        "}"
        :: "r"(addr), "r"(parity) : "memory");
}
__device__ __forceinline__ void st_async_f32(uint32_t remote_addr, float v,
                                             uint32_t remote_mbar) {
    asm volatile(
        "st.async.shared::cluster.mbarrier::complete_tx::bytes.f32 [%0], %1, [%2];"
        :: "r"(remote_addr), "f"(v), "r"(remote_mbar) : "memory");
}
__device__ __forceinline__ void cluster_arrive_() {
    asm volatile("barrier.cluster.arrive.aligned;" ::: "memory");
}
__device__ __forceinline__ void cluster_wait_() {
    asm volatile("barrier.cluster.wait.aligned;" ::: "memory");
}
__device__ __forceinline__ void fma2_(unsigned long long& acc,
                                      unsigned long long a, unsigned long long b) {
    asm("fma.rn.f32x2 %0, %1, %2, %0;" : "+l"(acc) : "l"(a), "l"(b));
}
__device__ __forceinline__ float hsum2_(unsigned long long v) {
    float lo, hi;
    asm("mov.b64 {%0, %1}, %2;" : "=f"(lo), "=f"(hi) : "l"(v));
    return lo + hi;
}
__device__ __forceinline__ float sigmoid_(float xv) {
    return __fdividef(1.0f, 1.0f + __expf(-xv));
}
__device__ __forceinline__ float tanh_(float xv) {
    return 1.0f - __fdividef(2.0f, __expf(2.0f * xv) + 1.0f);
}

__global__ void __launch_bounds__(NTHREADS, 1) scan_kernel(
    const float* __restrict__ Whh_e, const float* __restrict__ bhh_e,
    const float* __restrict__ Whh_d, const float* __restrict__ bhh_d,
    float* __restrict__ out)
{
    __shared__ __align__(16) float hbuf[2][H_];
    __shared__ __align__(8) unsigned long long mb[2];   // mb[b] guards hbuf[b]

    bool enc = (blockIdx.x >> 3) == 0;
    uint32_t crank;
    asm("mov.u32 %0, %%cluster_ctarank;" : "=r"(crank));

    const float* Whh = enc ? Whh_e : Whh_d;
    const float* bhh = enc ? bhh_e : bhh_d;
    const float* GI  = enc ? GI_enc : GI_dec;
    int    nsteps = enc ? ENC_STEPS : DEC_STEPS;
    float* outp   = enc ? out : (out + 240 * H_);

    int tid  = threadIdx.x;
    int w    = tid >> 5;
    int lane = tid & 31;
    int o    = lane >> 2;             // column slice / target CTA rank
    int jloc = w * 4 + (lane & 3);    // local output index 0..31
    int j    = (int)crank * 32 + jloc;

    // ---- load this thread's 96 weights as 48 packed f32x2 ----
    unsigned long long wr_[16], wz_[16], wn_[16];
    {
        const ulonglong2* Pr = (const ulonglong2*)(Whh + (size_t)j * H_ + o * 32);
        const ulonglong2* Pz = (const ulonglong2*)(Whh + (size_t)(256 + j) * H_ + o * 32);
        const ulonglong2* Pn = (const ulonglong2*)(Whh + (size_t)(512 + j) * H_ + o * 32);
#pragma unroll
        for (int k = 0; k < 8; k++) {
            ulonglong2 vr = Pr[k]; wr_[2*k] = vr.x; wr_[2*k+1] = vr.y;
            ulonglong2 vz = Pz[k]; wz_[2*k] = vz.x; wz_[2*k+1] = vz.y;
            ulonglong2 vn = Pn[k]; wn_[2*k] = vn.x; wn_[2*k+1] = vn.y;
        }
    }

    float bh_r = bhh[j];
    float bh_z = bhh[256 + j];
    float bh_n = bhh[512 + j];

    // remote addresses in CTA rank o: h slot + the two barriers
    uint32_t remH[2], remMB[2];
    remH[0]  = mapa_shared(smem_u32(&hbuf[0][j]), (uint32_t)o);
    remH[1]  = mapa_shared(smem_u32(&hbuf[1][j]), (uint32_t)o);
    remMB[0] = mapa_shared(smem_u32(&mb[0]), (uint32_t)o);
    remMB[1] = mapa_shared(smem_u32(&mb[1]), (uint32_t)o);
    uint32_t locMB[2] = { smem_u32(&mb[0]), smem_u32(&mb[1]) };

    // init: h0 = 0; barriers init (count=1) and pre-armed for their first use
    hbuf[0][tid] = 0.f;
    if (tid == 0) {
        mbar_init_(locMB[0], 1);
        mbar_init_(locMB[1], 1);
        mbar_arm_(locMB[0], TX_BYTES);   // first use: step 2 (h(1))
        mbar_arm_(locMB[1], TX_BYTES);   // first use: step 1 (h(0))
    }
    __syncthreads();
    cluster_arrive_();     // barrier inits visible before any remote st.async
    cluster_wait_();

    // gi prefetch ring, distance 2
    float g0r = __ldg(&GI[j]);
    float g0z = __ldg(&GI[256 + j]);
    float g0n = __ldg(&GI[512 + j]);
    float g1r = 0.f, g1z = 0.f, g1n = 0.f;
    if (nsteps > 1) {
        const float* g = GI + (size_t)G3;
        g1r = __ldg(&g[j]);
        g1z = __ldg(&g[256 + j]);
        g1n = __ldg(&g[512 + j]);
    }

    uint32_t par0 = 0, par1 = 0;   // per-barrier phase parity

    for (int s = 0; s < nsteps; s++) {
        int rd  = s & 1;          // h(s-1) lives in hbuf[rd], guarded by mb[rd]
        int wrb = rd ^ 1;         // h(s) goes to hbuf[wrb] / mb[wrb]

        // issue gi prefetch for s+2 BEFORE the wait (hides DRAM latency)
        float nr = 0.f, nz = 0.f, nn = 0.f;
        if ((s + 2) < nsteps) {
            const float* g = GI + (size_t)(s + 2) * G3;
            nr = __ldg(&g[j]);
            nz = __ldg(&g[256 + j]);
            nn = __ldg(&g[512 + j]);
        }

        if (s > 0) {
            // wait for h(s-1): all 1024 tx bytes + the pre-arm arrive
            if (rd) { mbar_wait_(locMB[1], par1); par1 ^= 1; }
            else    { mbar_wait_(locMB[0], par0); par0 ^= 1; }
            // re-arm this barrier for its next use (step s+2), new phase
            if (tid == 0) mbar_arm_(locMB[rd], TX_BYTES);
        }

        // ---- matvec over this thread's 32-col slice (3 rows) ----
        const ulonglong2* hp = (const ulonglong2*)(&hbuf[rd][o * 32]);
        float hold = hbuf[rd][j];
        unsigned long long ar0 = 0ull, ar1 = 0ull;
        unsigned long long az0 = 0ull, az1 = 0ull;
        unsigned long long an0 = 0ull, an1 = 0ull;
#pragma unroll
        for (int k = 0; k < 8; k++) {
            ulonglong2 hv = hp[k];
            fma2_(ar0, wr_[2*k], hv.x); fma2_(ar1, wr_[2*k+1], hv.y);
            fma2_(az0, wz_[2*k], hv.x); fma2_(az1, wz_[2*k+1], hv.y);
            fma2_(an0, wn_[2*k], hv.x); fma2_(an1, wn_[2*k+1], hv.y);
        }
        float pr = hsum2_(ar0) + hsum2_(ar1);
        float pz = hsum2_(az0) + hsum2_(az1);
        float pn = hsum2_(an0) + hsum2_(an1);

        // ---- butterfly reduce over the 8 column slices (lanes xor 4,8,16)
#pragma unroll
        for (int d = 4; d < 32; d <<= 1) {
            pr += __shfl_xor_sync(0xffffffffu, pr, d);
            pz += __shfl_xor_sync(0xffffffffu, pz, d);
            pn += __shfl_xor_sync(0xffffffffu, pn, d);
        }

        // ---- gates (every lane redundantly for its j) ----
        float r    = sigmoid_(g0r + pr + bh_r);
        float z    = sigmoid_(g0z + pz + bh_z);
        float n    = tanh_(g0n + r * (pn + bh_n));
        float hnew = n + z * (hold - n);   // (1-z)*n + z*h

        // ---- one st.async per thread: hnew(j) -> CTA o, signals its mb[wrb]
        if ((s + 1) < nsteps) {
            st_async_f32(remH[wrb], hnew, remMB[wrb]);
        }

        // ---- outputs (lane group o==0 only: unique j per store) ----
        if (o == 0) {
            if (enc) {
                if ((s & 127) == 127)
                    outp[(size_t)(s >> 7) * H_ + j] = hnew;
            } else {
                outp[(size_t)(s & 127) * (T_OUT * H_) + (size_t)(s >> 7) * H_ + j] = hnew;
            }
        }

        // rotate gi ring
        g0r = g1r; g0z = g1z; g0n = g1n;
        g1r = nr;  g1z = nz;  g1n = nn;
    }

    // safety: no CTA exits while peers may still address its SMEM
    cluster_arrive_();
    cluster_wait_();
}

// ---------------------------------------------------------------------------
// Launch
// ---------------------------------------------------------------------------
extern "C" void kernel_launch(void* const* d_in, const int* in_sizes, int n_in,
                              void* d_out, int out_size)
{
    const float* x     = (const float*)d_in[0];
    const float* Wih_e = (const float*)d_in[1];
    const float* Whh_e = (const float*)d_in[2];
    const float* bih_e = (const float*)d_in[3];
    const float* bhh_e = (const float*)d_in[4];
    const float* Wih_d = (const float*)d_in[5];
    const float* Whh_d = (const float*)d_in[6];
    const float* bih_d = (const float*)d_in[7];
    const float* bhh_d = (const float*)d_in[8];
    float* out = (float*)d_out;

    gi_kernel<<<ENC_BLOCKS + DEC_BLOCKS, 768>>>(x, Wih_e, bih_e, Wih_d, bih_d);

    cudaLaunchConfig_t cfg = {};
    cfg.gridDim  = dim3(2 * CLUSTER, 1, 1);
    cfg.blockDim = dim3(NTHREADS, 1, 1);
    cfg.dynamicSmemBytes = 0;
    cfg.stream = 0;
    cudaLaunchAttribute attrs[1];
    attrs[0].id = cudaLaunchAttributeClusterDimension;
    attrs[0].val.clusterDim.x = CLUSTER;
    attrs[0].val.clusterDim.y = 1;
    attrs[0].val.clusterDim.z = 1;
    cfg.attrs = attrs;
    cfg.numAttrs = 1;
    cudaLaunchKernelEx(&cfg, scan_kernel, Whh_e, bhh_e, Whh_d, bhh_d, out);
}

// round 7
// speedup vs baseline: 1.8192x; 1.2347x over previous
#include <cuda_runtime.h>
#include <cstdint>

// Problem constants
#define B_       128
#define T_IN     240
#define T_OUT    30
#define D_       128
#define H_       256
#define G3       768              // 3*H
#define STRIDE_  8
#define ENC_STEPS (T_IN * B_)     // 30720
#define DEC_STEPS (T_OUT * B_)    // 3840

// Scratch: precomputed input projections gi = x @ Wih^T + b_ih
__device__ float GI_enc[ENC_STEPS * G3];   // ~94.4 MB
__device__ float GI_dec[DEC_STEPS * G3];   // ~11.8 MB

// ---------------------------------------------------------------------------
// Kernel 1: GI GEMM.  GI[s][row] = b_ih[row] + sum_d X[s,d] * Wih[row][d]
// ---------------------------------------------------------------------------
#define S_TILE     32
#define ENC_BLOCKS (ENC_STEPS / S_TILE)   // 960
#define DEC_BLOCKS (DEC_STEPS / S_TILE)   // 120

__global__ void __launch_bounds__(768, 1) gi_kernel(
    const float* __restrict__ x,
    const float* __restrict__ Wih_e, const float* __restrict__ bih_e,
    const float* __restrict__ Wih_d, const float* __restrict__ bih_d)
{
    __shared__ __align__(16) float Xs[S_TILE][D_];   // 16 KB

    bool enc = blockIdx.x < ENC_BLOCKS;
    int  sblk = enc ? blockIdx.x : blockIdx.x - ENC_BLOCKS;
    int  s0   = sblk * S_TILE;
    const float* W   = enc ? Wih_e : Wih_d;
    const float* bih = enc ? bih_e : bih_d;
    float*       GI  = enc ? GI_enc : GI_dec;
    int tstride = enc ? 1 : STRIDE_;

    int tid = threadIdx.x;

    for (int idx = tid; idx < S_TILE * D_; idx += 768) {
        int i = idx >> 7;
        int k = idx & 127;
        int s = s0 + i;
        int b = s & 127;
        int t = (s >> 7) * tstride;
        Xs[i][k] = x[(size_t)b * (T_IN * D_) + (size_t)t * D_ + k];
    }
    __syncthreads();

    int row = tid;
    const float4* W4 = (const float4*)(W + (size_t)row * D_);

    float acc[S_TILE];
#pragma unroll
    for (int i = 0; i < S_TILE; i++) acc[i] = 0.f;

#pragma unroll 4
    for (int kk = 0; kk < D_ / 4; kk++) {
        float4 w = W4[kk];
#pragma unroll
        for (int i = 0; i < S_TILE; i++) {
            float4 xv = ((const float4*)Xs[i])[kk];
            acc[i] += w.x * xv.x + w.y * xv.y + w.z * xv.z + w.w * xv.w;
        }
    }

    float bv = bih[row];
#pragma unroll
    for (int i = 0; i < S_TILE; i++)
        GI[(size_t)(s0 + i) * G3 + row] = acc[i] + bv;
}

// ---------------------------------------------------------------------------
// Kernel 2: serial GRU scans.  8-CTA cluster, register-resident W_hh,
// st.async cross-CTA exchange (data + tx signal in one op), 2 ping-pong
// mbarriers.  128 threads/CTA (1 warp per SMSP).
//
// Thread layout:
//   warp w (0..3), lane: o = lane>>3 (column slice 0..3, 64 cols each),
//   jq = lane&7, j = crank*32 + w*8 + jq.
// Each thread: rows {j, 256+j, 512+j} x cols [o*64, o*64+64) = 192 weights
// (96 packed f32x2 registers).
// Reduce: 2-round shfl butterfly (xor 8, 16).  All 4 lanes of a j then hold
// identical gh(r,z,n); gates computed redundantly; hold carried in register.
// Send: pair lanes exchange hnew (shfl.xor 1); even-jq lanes send ONE b64
// (two adjacent GLOBAL j) to CTA o and CTA o+4.  128 msgs -> 1024 tx bytes.
// ---------------------------------------------------------------------------
#define CLUSTER  8
#define NTHREADS 128
#define TX_BYTES (H_ * 4)   // 1024

__device__ __forceinline__ uint32_t smem_u32(const void* p) {
    return (uint32_t)__cvta_generic_to_shared(p);
}
__device__ __forceinline__ uint32_t mapa_shared(uint32_t addr, uint32_t rank) {
    uint32_t r;
    asm volatile("mapa.shared::cluster.u32 %0, %1, %2;" : "=r"(r) : "r"(addr), "r"(rank));
    return r;
}
__device__ __forceinline__ void mbar_init_(uint32_t addr, uint32_t count) {
    asm volatile("mbarrier.init.shared.b64 [%0], %1;" :: "r"(addr), "r"(count) : "memory");
}
__device__ __forceinline__ void mbar_arm_(uint32_t addr, uint32_t tx) {
    asm volatile("mbarrier.arrive.expect_tx.shared.b64 _, [%0], %1;"
                 :: "r"(addr), "r"(tx) : "memory");
}
__device__ __forceinline__ void mbar_wait_(uint32_t addr, uint32_t parity) {
    asm volatile(
        "{\n\t"
        ".reg .pred P;\n\t"
        "W_%=:\n\t"
        "mbarrier.try_wait.parity.shared.b64 P, [%0], %1, 0x989680;\n\t"
        "@!P bra W_%=;\n\t"
        "}"
        :: "r"(addr), "r"(parity) : "memory");
}
__device__ __forceinline__ void st_async_b64(uint32_t remote_addr, unsigned long long v,
                                             uint32_t remote_mbar) {
    asm volatile(
        "st.async.shared::cluster.mbarrier::complete_tx::bytes.b64 [%0], %1, [%2];"
        :: "r"(remote_addr), "l"(v), "r"(remote_mbar) : "memory");
}
__device__ __forceinline__ void cluster_arrive_() {
    asm volatile("barrier.cluster.arrive.aligned;" ::: "memory");
}
__device__ __forceinline__ void cluster_wait_() {
    asm volatile("barrier.cluster.wait.aligned;" ::: "memory");
}
__device__ __forceinline__ void fma2_(unsigned long long& acc,
                                      unsigned long long a, unsigned long long b) {
    asm("fma.rn.f32x2 %0, %1, %2, %0;" : "+l"(acc) : "l"(a), "l"(b));
}
__device__ __forceinline__ float hsum2_(unsigned long long v) {
    float lo, hi;
    asm("mov.b64 {%0, %1}, %2;" : "=f"(lo), "=f"(hi) : "l"(v));
    return lo + hi;
}
__device__ __forceinline__ unsigned long long pack2_(float lo, float hi) {
    unsigned long long v;
    asm("mov.b64 %0, {%1, %2};" : "=l"(v) : "f"(lo), "f"(hi));
    return v;
}
__device__ __forceinline__ float sigmoid_(float xv) {
    return __fdividef(1.0f, 1.0f + __expf(-xv));
}
__device__ __forceinline__ float tanh_(float xv) {
    return 1.0f - __fdividef(2.0f, __expf(2.0f * xv) + 1.0f);
}

__global__ void __launch_bounds__(NTHREADS, 1) scan_kernel(
    const float* __restrict__ Whh_e, const float* __restrict__ bhh_e,
    const float* __restrict__ Whh_d, const float* __restrict__ bhh_d,
    float* __restrict__ out)
{
    __shared__ __align__(16) float hbuf[2][H_];
    __shared__ __align__(8) unsigned long long mb[2];   // mb[b] guards hbuf[b]

    bool enc = (blockIdx.x >> 3) == 0;
    uint32_t crank;
    asm("mov.u32 %0, %%cluster_ctarank;" : "=r"(crank));

    const float* Whh = enc ? Whh_e : Whh_d;
    const float* bhh = enc ? bhh_e : bhh_d;
    const float* GI  = enc ? GI_enc : GI_dec;
    int    nsteps = enc ? ENC_STEPS : DEC_STEPS;
    float* outp   = enc ? out : (out + 240 * H_);

    int tid  = threadIdx.x;
    int w    = tid >> 5;
    int lane = tid & 31;
    int o    = lane >> 3;             // column slice (0..3): cols [o*64, o*64+64)
    int jq   = lane & 7;
    int jloc = w * 8 + jq;            // local output index 0..31
    int j    = (int)crank * 32 + jloc;

    // ---- load this thread's 192 weights as 96 packed f32x2 ----
    unsigned long long wr_[32], wz_[32], wn_[32];
    {
        const ulonglong2* Pr = (const ulonglong2*)(Whh + (size_t)j * H_ + o * 64);
        const ulonglong2* Pz = (const ulonglong2*)(Whh + (size_t)(256 + j) * H_ + o * 64);
        const ulonglong2* Pn = (const ulonglong2*)(Whh + (size_t)(512 + j) * H_ + o * 64);
#pragma unroll
        for (int k = 0; k < 16; k++) {
            ulonglong2 vr = Pr[k]; wr_[2*k] = vr.x; wr_[2*k+1] = vr.y;
            ulonglong2 vz = Pz[k]; wz_[2*k] = vz.x; wz_[2*k+1] = vz.y;
            ulonglong2 vn = Pn[k]; wn_[2*k] = vn.x; wn_[2*k+1] = vn.y;
        }
    }

    float bh_r = bhh[j];
    float bh_z = bhh[256 + j];
    float bh_n = bhh[512 + j];

    // remote addresses: even-jq lanes send the pair [j&~1, j|1] (GLOBAL h
    // indices) as one b64 to CTA o and CTA o+4.
    int jpair = j & ~1;   // FIX (R5 bug): global index, includes crank*32
    uint32_t remH[2][2], remMB[2][2];
    {
        uint32_t a0 = smem_u32(&hbuf[0][jpair]);
        uint32_t a1 = smem_u32(&hbuf[1][jpair]);
        uint32_t m0 = smem_u32(&mb[0]);
        uint32_t m1 = smem_u32(&mb[1]);
        remH[0][0]  = mapa_shared(a0, (uint32_t)o);
        remH[0][1]  = mapa_shared(a0, (uint32_t)(o + 4));
        remH[1][0]  = mapa_shared(a1, (uint32_t)o);
        remH[1][1]  = mapa_shared(a1, (uint32_t)(o + 4));
        remMB[0][0] = mapa_shared(m0, (uint32_t)o);
        remMB[0][1] = mapa_shared(m0, (uint32_t)(o + 4));
        remMB[1][0] = mapa_shared(m1, (uint32_t)o);
        remMB[1][1] = mapa_shared(m1, (uint32_t)(o + 4));
    }
    uint32_t locMB[2] = { smem_u32(&mb[0]), smem_u32(&mb[1]) };

    // init: h0 = 0; barriers init (count=1) and pre-armed for first use
    hbuf[0][tid] = 0.f;
    hbuf[0][tid + 128] = 0.f;
    if (tid == 0) {
        mbar_init_(locMB[0], 1);
        mbar_init_(locMB[1], 1);
        mbar_arm_(locMB[0], TX_BYTES);   // first use: step 2 (h(1))
        mbar_arm_(locMB[1], TX_BYTES);   // first use: step 1 (h(0))
    }
    __syncthreads();
    cluster_arrive_();     // barrier inits visible before any remote st.async
    cluster_wait_();

    // gi prefetch ring, distance 2
    float g0r = __ldg(&GI[j]);
    float g0z = __ldg(&GI[256 + j]);
    float g0n = __ldg(&GI[512 + j]);
    float g1r = 0.f, g1z = 0.f, g1n = 0.f;
    if (nsteps > 1) {
        const float* g = GI + (size_t)G3;
        g1r = __ldg(&g[j]);
        g1z = __ldg(&g[256 + j]);
        g1n = __ldg(&g[512 + j]);
    }

    uint32_t par0 = 0, par1 = 0;   // per-barrier phase parity
    float hold = 0.f;              // h[j], carried in register
    bool sender = ((jq & 1) == 0);

    for (int s = 0; s < nsteps; s++) {
        int rd  = s & 1;          // h(s-1) lives in hbuf[rd], guarded by mb[rd]
        int wrb = rd ^ 1;         // h(s) goes to hbuf[wrb] / mb[wrb]

        // issue gi prefetch for s+2 BEFORE the wait (hides DRAM latency)
        float nr = 0.f, nz = 0.f, nn = 0.f;
        if ((s + 2) < nsteps) {
            const float* g = GI + (size_t)(s + 2) * G3;
            nr = __ldg(&g[j]);
            nz = __ldg(&g[256 + j]);
            nn = __ldg(&g[512 + j]);
        }

        if (s > 0) {
            if (rd) { mbar_wait_(locMB[1], par1); par1 ^= 1; }
            else    { mbar_wait_(locMB[0], par0); par0 ^= 1; }
            // re-arm this barrier for its next use (step s+2), new phase
            if (tid == 0) mbar_arm_(locMB[rd], TX_BYTES);
        }

        // ---- matvec over this thread's 64-col slice (3 rows) ----
        const ulonglong2* hp = (const ulonglong2*)(&hbuf[rd][o * 64]);
        unsigned long long ar0 = 0ull, ar1 = 0ull;
        unsigned long long az0 = 0ull, az1 = 0ull;
        unsigned long long an0 = 0ull, an1 = 0ull;
#pragma unroll
        for (int k = 0; k < 16; k++) {
            ulonglong2 hv = hp[k];
            fma2_(ar0, wr_[2*k], hv.x); fma2_(ar1, wr_[2*k+1], hv.y);
            fma2_(az0, wz_[2*k], hv.x); fma2_(az1, wz_[2*k+1], hv.y);
            fma2_(an0, wn_[2*k], hv.x); fma2_(an1, wn_[2*k+1], hv.y);
        }
        float pr = hsum2_(ar0) + hsum2_(ar1);
        float pz = hsum2_(az0) + hsum2_(az1);
        float pn = hsum2_(an0) + hsum2_(an1);

        // ---- butterfly reduce over the 4 column slices (lanes xor 8,16)
#pragma unroll
        for (int d = 8; d < 32; d <<= 1) {
            pr += __shfl_xor_sync(0xffffffffu, pr, d);
            pz += __shfl_xor_sync(0xffffffffu, pz, d);
            pn += __shfl_xor_sync(0xffffffffu, pn, d);
        }

        // ---- gates (all 4 lanes of a j redundantly) ----
        float r    = sigmoid_(g0r + pr + bh_r);
        float z    = sigmoid_(g0z + pz + bh_z);
        float n    = tanh_(g0n + r * (pn + bh_n));
        float hnew = n + z * (hold - n);   // (1-z)*n + z*h
        hold = hnew;

        // ---- pack pair (j even, j odd) and send b64 to CTA o and o+4 ----
        float partner = __shfl_xor_sync(0xffffffffu, hnew, 1);
        if ((s + 1) < nsteps && sender) {
            unsigned long long v = pack2_(hnew, partner);   // lo = even j = own
            st_async_b64(remH[wrb][0], v, remMB[wrb][0]);
            st_async_b64(remH[wrb][1], v, remMB[wrb][1]);
        }

        // ---- outputs (lane group o==0 only: unique j per store) ----
        if (o == 0) {
            if (enc) {
                if ((s & 127) == 127)
                    outp[(size_t)(s >> 7) * H_ + j] = hnew;
            } else {
                outp[(size_t)(s & 127) * (T_OUT * H_) + (size_t)(s >> 7) * H_ + j] = hnew;
            }
        }

        // rotate gi ring
        g0r = g1r; g0z = g1z; g0n = g1n;
        g1r = nr;  g1z = nz;  g1n = nn;
    }

    // safety: no CTA exits while peers may still address its SMEM
    cluster_arrive_();
    cluster_wait_();
}

// ---------------------------------------------------------------------------
// Launch
// ---------------------------------------------------------------------------
extern "C" void kernel_launch(void* const* d_in, const int* in_sizes, int n_in,
                              void* d_out, int out_size)
{
    const float* x     = (const float*)d_in[0];
    const float* Wih_e = (const float*)d_in[1];
    const float* Whh_e = (const float*)d_in[2];
    const float* bih_e = (const float*)d_in[3];
    const float* bhh_e = (const float*)d_in[4];
    const float* Wih_d = (const float*)d_in[5];
    const float* Whh_d = (const float*)d_in[6];
    const float* bih_d = (const float*)d_in[7];
    const float* bhh_d = (const float*)d_in[8];
    float* out = (float*)d_out;

    gi_kernel<<<ENC_BLOCKS + DEC_BLOCKS, 768>>>(x, Wih_e, bih_e, Wih_d, bih_d);

    cudaLaunchConfig_t cfg = {};
    cfg.gridDim  = dim3(2 * CLUSTER, 1, 1);
    cfg.blockDim = dim3(NTHREADS, 1, 1);
    cfg.dynamicSmemBytes = 0;
    cfg.stream = 0;
    cudaLaunchAttribute attrs[1];
    attrs[0].id = cudaLaunchAttributeClusterDimension;
    attrs[0].val.clusterDim.x = CLUSTER;
    attrs[0].val.clusterDim.y = 1;
    attrs[0].val.clusterDim.z = 1;
    cfg.attrs = attrs;
    cfg.numAttrs = 1;
    cudaLaunchKernelEx(&cfg, scan_kernel, Whh_e, bhh_e, Whh_d, bhh_d, out);
}